// round 4
// baseline (speedup 1.0000x reference)
#include <cuda_runtime.h>
#include <cuda_bf16.h>

#define BSZ 8
#define LEN 2048
#define HID 1024
#define NH  16
#define HD  64
#define MTOT (BSZ*LEN)      /* 16384 */
#define NKV  (NH*HD)        /* 1024  */
#define MARGIN 4e-3f

#define BM 128
#define BN 128
#define BK 32
#define NSEG 3
#define KITER (HID/BK)          /* 32 */
#define NITER (NSEG*KITER)      /* 96 */
#define STAGES 3
#define STAGE_BYTES 16384       /* A 8KB + B 8KB */

// ---------------- scratch (device globals; allocation-free rule) ------------
__device__ float g_V1[(size_t)MTOT * NKV];
__device__ __nv_bfloat16 g_Ahi[(size_t)MTOT * HID];
__device__ __nv_bfloat16 g_Amid[(size_t)MTOT * HID];
__device__ __nv_bfloat16 g_WhiV[(size_t)NKV * HID];   // [n][k] K-major
__device__ __nv_bfloat16 g_WmidV[(size_t)NKV * HID];
__device__ __nv_bfloat16 g_WhiK[(size_t)NKV * HID];
__device__ __nv_bfloat16 g_WmidK[(size_t)NKV * HID];
__device__ unsigned char g_valid[MTOT * NH];
__device__ int2 g_fm[MTOT * NH];
__device__ int2 g_bm[MTOT * NH];
__device__ int g_fixcnt;
__device__ int g_fixlist[MTOT * NH];

// SW64 swizzle for 64-byte rows (4x 16B chunks): chunk ^= (row>>1)&3
#define SWZ64(row, chunk) ((row) * 64 + (((chunk) ^ (((row) >> 1) & 3)) << 4))

__device__ __forceinline__ unsigned smem_u32(const void* p) {
    unsigned a;
    asm("{ .reg .u64 t; cvta.to.shared.u64 t, %1; cvt.u32.u64 %0, t; }" : "=r"(a) : "l"(p));
    return a;
}
#define LDSM_X4(r0, r1, r2, r3, addr) \
    asm volatile("ldmatrix.sync.aligned.m8n8.x4.shared.b16 {%0,%1,%2,%3},[%4];" \
        : "=r"(r0), "=r"(r1), "=r"(r2), "=r"(r3) : "r"(addr))
#define MMA16816(c, a0, a1, a2, a3, b0, b1) \
    asm volatile("mma.sync.aligned.m16n8k16.row.col.f32.bf16.bf16.f32 " \
        "{%0,%1,%2,%3},{%4,%5,%6,%7},{%8,%9},{%0,%1,%2,%3};" \
        : "+f"((c)[0]), "+f"((c)[1]), "+f"((c)[2]), "+f"((c)[3]) \
        : "r"(a0), "r"(a1), "r"(a2), "r"(a3), "r"(b0), "r"(b1))
#define CP_ASYNC16(dst, src) \
    asm volatile("cp.async.cg.shared.global [%0], [%1], 16;" :: "r"(dst), "l"(src))
#define CP_COMMIT() asm volatile("cp.async.commit_group;")
#define CP_WAIT1()  asm volatile("cp.async.wait_group 1;")

// ---------------------------------------------------------------------------
__global__ void init_kernel() { if (threadIdx.x == 0) g_fixcnt = 0; }

// split hidden_states -> hi/mid bf16 (each thread: 8 consecutive k)
__global__ void splitA_kernel(const float* __restrict__ hs)
{
    const size_t t = (size_t)blockIdx.x * blockDim.x + threadIdx.x;
    const size_t o = t * 8;
    float4 x0 = *(const float4*)(hs + o);
    float4 x1 = *(const float4*)(hs + o + 4);
    float xs[8] = {x0.x, x0.y, x0.z, x0.w, x1.x, x1.y, x1.z, x1.w};
    union { __nv_bfloat16 b[8]; uint4 u; } h, md;
    #pragma unroll
    for (int i = 0; i < 8; i++) {
        h.b[i]  = __float2bfloat16(xs[i]);
        md.b[i] = __float2bfloat16(xs[i] - __bfloat162float(h.b[i]));
    }
    *(uint4*)(g_Ahi + o)  = h.u;
    *(uint4*)(g_Amid + o) = md.u;
}

// transpose + split weights: W[k][n] f32 -> out[n][k] bf16 hi/mid
__global__ void splitW_kernel(const float* __restrict__ Wv, const float* __restrict__ Wk)
{
    __shared__ float s[32][33];
    const float* W = blockIdx.z ? Wk : Wv;
    __nv_bfloat16* Ohi  = blockIdx.z ? g_WhiK  : g_WhiV;
    __nv_bfloat16* Omid = blockIdx.z ? g_WmidK : g_WmidV;
    const int kb = blockIdx.x * 32, nb = blockIdx.y * 32;
    const int c = threadIdx.x & 31, r0 = threadIdx.x >> 5;
    #pragma unroll
    for (int j = 0; j < 4; j++) {
        int r = r0 + j * 8;
        s[r][c] = W[(size_t)(kb + r) * NKV + nb + c];
    }
    __syncthreads();
    #pragma unroll
    for (int j = 0; j < 4; j++) {
        int r = r0 + j * 8;
        float x = s[c][r];
        __nv_bfloat16 hb = __float2bfloat16(x);
        Ohi [(size_t)(nb + r) * HID + kb + c] = hb;
        Omid[(size_t)(nb + r) * HID + kb + c] = __float2bfloat16(x - __bfloat162float(hb));
    }
}

// ---------------------------------------------------------------------------
// HMMA GEMM, cp.async 3-stage pipeline. CTA = 128(m) x 128(n).
//   grid.x 0..7  : V path     grid.x 8..15 : K path (fused dots)
// ---------------------------------------------------------------------------
__global__ __launch_bounds__(256, 2)
void mma_kernel(const float* __restrict__ biasV, const float* __restrict__ biasK,
                const float* __restrict__ RH)
{
    __shared__ __align__(1024) unsigned char smem_buf[STAGES * STAGE_BYTES];
    const unsigned sBase = smem_u32(smem_buf);

    const int tid = threadIdx.x;
    const int lane = tid & 31, wid = tid >> 5;
    const int warpM = wid & 1, warpN = wid >> 1;      // 2 x 4 warps, tile 64x32
    const int z  = blockIdx.x >> 3;
    const int n0 = (blockIdx.x & 7) * BN;
    const int m0 = blockIdx.y * BM;

    const __nv_bfloat16* Whi  = z ? g_WhiK  : g_WhiV;
    const __nv_bfloat16* Wmid = z ? g_WmidK : g_WmidV;

    // loader mapping: thread t -> rows (t>>2, t>>2+64), chunk t&3
    const int lr = tid >> 2;
    const int lc = tid & 3;
    const unsigned dA0 = SWZ64(lr, lc);
    const unsigned dA1 = SWZ64(lr + 64, lc);
    const size_t gOffA0 = (size_t)(m0 + lr) * (HID * 2) + lc * 16;
    const size_t gOffA1 = (size_t)(m0 + lr + 64) * (HID * 2) + lc * 16;
    const size_t gOffB0 = (size_t)(n0 + lr) * (HID * 2) + lc * 16;
    const size_t gOffB1 = (size_t)(n0 + lr + 64) * (HID * 2) + lc * 16;

    float acc[4][4][4];
    #pragma unroll
    for (int i = 0; i < 4; i++)
        #pragma unroll
        for (int j = 0; j < 4; j++)
            #pragma unroll
            for (int q = 0; q < 4; q++) acc[i][j][q] = 0.f;

    // issue one stage's cp.asyncs
    auto issue = [&](int it) {
        const int seg = it >> 5;                  // 0,1,2
        const int kc  = it & 31;
        const char* aS = (const char*)((seg == 2) ? g_Amid : g_Ahi) + kc * 64;
        const char* bS = (const char*)((seg == 1) ? Wmid : Whi) + kc * 64;
        const unsigned st = sBase + (it % STAGES) * STAGE_BYTES;
        CP_ASYNC16(st + dA0, aS + gOffA0);
        CP_ASYNC16(st + dA1, aS + gOffA1);
        CP_ASYNC16(st + 8192 + dA0, bS + gOffB0);
        CP_ASYNC16(st + 8192 + dA1, bS + gOffB1);
    };

    issue(0); CP_COMMIT();
    issue(1); CP_COMMIT();

    const int aRowBase = warpM * 64 + (lane & 15);
    const int bRowBase = warpN * 32 + (lane & 15);
    const int khalf = lane >> 4;

    for (int it = 0; it < NITER; it++) {
        CP_WAIT1();
        __syncthreads();
        if (it + 2 < NITER) issue(it + 2);
        CP_COMMIT();

        const unsigned stA = sBase + (it % STAGES) * STAGE_BYTES;
        const unsigned stB = stA + 8192;
        #pragma unroll
        for (int ks = 0; ks < 2; ks++) {
            const int chunk = ks * 2 + khalf;
            unsigned af[4][4], bf[2][4];
            #pragma unroll
            for (int mf = 0; mf < 4; mf++) {
                int row = aRowBase + mf * 16;
                LDSM_X4(af[mf][0], af[mf][1], af[mf][2], af[mf][3], stA + SWZ64(row, chunk));
            }
            #pragma unroll
            for (int nb = 0; nb < 2; nb++) {
                int row = bRowBase + nb * 16;
                LDSM_X4(bf[nb][0], bf[nb][1], bf[nb][2], bf[nb][3], stB + SWZ64(row, chunk));
            }
            #pragma unroll
            for (int mf = 0; mf < 4; mf++)
                #pragma unroll
                for (int nf = 0; nf < 4; nf++) {
                    unsigned b0 = bf[nf >> 1][(nf & 1) ? 1 : 0];
                    unsigned b1 = bf[nf >> 1][(nf & 1) ? 3 : 2];
                    MMA16816(acc[mf][nf], af[mf][0], af[mf][1], af[mf][2], af[mf][3], b0, b1);
                }
        }
    }

    // ---------------- epilogue ----------------
    const int rBase = m0 + warpM * 64 + (lane >> 2);
    const int cBase = n0 + warpN * 32 + (lane & 3) * 2;

    if (z == 0) {
        #pragma unroll
        for (int mf = 0; mf < 4; mf++) {
            #pragma unroll
            for (int nf = 0; nf < 4; nf++) {
                int col = cBase + nf * 8;
                float b0 = biasV[col], b1 = biasV[col + 1];
                int r0 = rBase + mf * 16;
                float2 v;
                v.x = fmaxf(acc[mf][nf][0] + b0, 0.f);
                v.y = fmaxf(acc[mf][nf][1] + b1, 0.f);
                *(float2*)(g_V1 + (size_t)r0 * NKV + col) = v;
                v.x = fmaxf(acc[mf][nf][2] + b0, 0.f);
                v.y = fmaxf(acc[mf][nf][3] + b1, 0.f);
                *(float2*)(g_V1 + (size_t)(r0 + 8) * NKV + col) = v;
            }
        }
    } else {
        __syncthreads();
        float* sdots = (float*)smem_buf;       // [128][2]
        if (tid < 256) sdots[tid] = 0.f;
        __syncthreads();
        const int hloc = warpN >> 1;
        #pragma unroll
        for (int mf = 0; mf < 4; mf++) {
            float slo = 0.f, shi = 0.f;
            #pragma unroll
            for (int nf = 0; nf < 4; nf++) {
                int col = cBase + nf * 8;
                float b0 = biasK[col], b1 = biasK[col + 1];
                float w0 = RH[col],   w1 = RH[col + 1];
                slo += fmaxf(acc[mf][nf][0] + b0, 0.f) * w0
                     + fmaxf(acc[mf][nf][1] + b1, 0.f) * w1;
                shi += fmaxf(acc[mf][nf][2] + b0, 0.f) * w0
                     + fmaxf(acc[mf][nf][3] + b1, 0.f) * w1;
            }
            slo += __shfl_xor_sync(0xffffffffu, slo, 1);
            slo += __shfl_xor_sync(0xffffffffu, slo, 2);
            shi += __shfl_xor_sync(0xffffffffu, shi, 1);
            shi += __shfl_xor_sync(0xffffffffu, shi, 2);
            if ((lane & 3) == 0) {
                int rloc = warpM * 64 + mf * 16 + (lane >> 2);
                atomicAdd(&sdots[rloc * 2 + hloc], slo);
                atomicAdd(&sdots[(rloc + 8) * 2 + hloc], shi);
            }
        }
        __syncthreads();
        if (tid < 256) {
            int rloc = tid >> 1, h = tid & 1;
            int m = m0 + rloc;
            int n = (n0 >> 6) + h;
            float dd = sdots[tid];
            int o = m * NH + n;
            if (fabsf(dd - 0.5f) < MARGIN) {
                int ix = atomicAdd(&g_fixcnt, 1);
                g_fixlist[ix] = (m << 4) | n;
                g_valid[o] = 0;
            } else {
                g_valid[o] = (dd > 0.5f) ? 1 : 0;
            }
        }
    }
}

// ---------------------------------------------------------------------------
// exact fp32 recompute near threshold: one warp per item, coalesced W rows
// ---------------------------------------------------------------------------
__global__ void fix_kernel(const float* __restrict__ hs, const float* __restrict__ K1w,
                           const float* __restrict__ K1b, const float* __restrict__ RH)
{
    const int cnt = g_fixcnt;
    const int w = blockIdx.x * (blockDim.x >> 5) + (threadIdx.x >> 5);
    const int lane = threadIdx.x & 31;
    const int nw = gridDim.x * (blockDim.x >> 5);
    for (int i = w; i < cnt; i += nw) {
        int mn = g_fixlist[i];
        int m = mn >> 4, n = mn & 15;
        const float* a  = hs + (size_t)m * HID;
        const float* wp = K1w + n * HD + lane;
        float a0 = 0.f, a1 = 0.f;
        #pragma unroll 4
        for (int k = 0; k < HID; k++) {
            float av = __ldg(a + k);
            a0 = fmaf(av, __ldg(wp + (size_t)k * NKV), a0);
            a1 = fmaf(av, __ldg(wp + (size_t)k * NKV + 32), a1);
        }
        float d = fmaxf(a0 + K1b[n * HD + lane], 0.f) * RH[n * HD + lane]
                + fmaxf(a1 + K1b[n * HD + lane + 32], 0.f) * RH[n * HD + lane + 32];
        #pragma unroll
        for (int o = 16; o; o >>= 1) d += __shfl_xor_sync(0xffffffffu, d, o);
        if (lane == 0) g_valid[m * NH + n] = (d > 0.5f) ? 1 : 0;
    }
}

// ---------------------------------------------------------------------------
__global__ void scan_kernel()
{
    __shared__ unsigned char sv[LEN];
    __shared__ int2 sf[LEN];
    __shared__ int2 sb[LEN];
    const int b = blockIdx.x >> 4;
    const int n = blockIdx.x & 15;

    for (int l = threadIdx.x; l < LEN; l += blockDim.x)
        sv[l] = g_valid[(size_t)(b * LEN + l) * NH + n];
    __syncthreads();

    if (threadIdx.x == 0) {
        int a = 0, bb = 0;
        sf[0] = make_int2(0, 0);
        for (int l = 1; l < LEN; l++) {
            if (sv[l]) { bb = a; a = l; }
            sf[l] = make_int2(a, bb);
        }
    } else if (threadIdx.x == 32) {
        int a = LEN - 1, bb = LEN - 1;
        sb[LEN - 1] = make_int2(LEN - 1, LEN - 1);
        for (int l = LEN - 2; l >= 0; l--) {
            if (sv[l]) { bb = a; a = (LEN - 1) - l; }
            sb[l] = make_int2(a, bb);
        }
    }
    __syncthreads();

    for (int l = threadIdx.x; l < LEN; l += blockDim.x) {
        const size_t o = (size_t)(b * LEN + l) * NH + n;
        g_fm[o] = sf[l];
        g_bm[o] = sb[l];
    }
}

// ---------------------------------------------------------------------------
__global__ void gather_kernel(const float* __restrict__ bw, float* __restrict__ out)
{
    const int t = blockIdx.x * blockDim.x + threadIdx.x;
    const int h4 = t & 15;
    const int n  = (t >> 4) & 15;
    const int m  = t >> 8;
    if (m >= MTOT) return;
    const int b = m >> 11;
    const size_t io = (size_t)m * NH + n;
    const int2 f  = g_fm[io];
    const int2 bk = g_bm[io];
    const float4 w = *(const float4*)(bw + n * 4);
    const int base = b * LEN;
    const int col = n * HD + h4 * 4;
    const float4 v0 = *(const float4*)(g_V1 + (size_t)(base + f.x)  * NKV + col);
    const float4 v1 = *(const float4*)(g_V1 + (size_t)(base + f.y)  * NKV + col);
    const float4 v2 = *(const float4*)(g_V1 + (size_t)(base + bk.x) * NKV + col);
    const float4 v3 = *(const float4*)(g_V1 + (size_t)(base + bk.y) * NKV + col);
    float4 rr;
    rr.x = w.x * v0.x + w.y * v1.x + w.z * v2.x + w.w * v3.x;
    rr.y = w.x * v0.y + w.y * v1.y + w.z * v2.y + w.w * v3.y;
    rr.z = w.x * v0.z + w.y * v1.z + w.z * v2.z + w.w * v3.z;
    rr.w = w.x * v0.w + w.y * v1.w + w.z * v2.w + w.w * v3.w;
    *(float4*)(out + (size_t)m * NKV + col) = rr;
}

// ---------------------------------------------------------------------------
extern "C" void kernel_launch(void* const* d_in, const int* in_sizes, int n_in,
                              void* d_out, int out_size)
{
    const float* hs  = (const float*)d_in[0];
    const float* K1w = (const float*)d_in[1];
    const float* K1b = (const float*)d_in[2];
    const float* V1w = (const float*)d_in[3];
    const float* V1b = (const float*)d_in[4];
    const float* bw  = (const float*)d_in[5];
    const float* RH  = (const float*)d_in[6];
    float* out = (float*)d_out;

    init_kernel<<<1, 32>>>();
    splitA_kernel<<<(MTOT * HID / 8) / 256, 256>>>(hs);
    splitW_kernel<<<dim3(32, 32, 2), 256>>>(V1w, K1w);
    mma_kernel<<<dim3(16, MTOT / BM), 256>>>(V1b, K1b, RH);
    fix_kernel<<<256, 256>>>(hs, K1w, K1b, RH);
    scan_kernel<<<BSZ * NH, 128>>>();
    gather_kernel<<<(MTOT * NH * 16) / 256, 256>>>(bw, out);
}

// round 5
// speedup vs baseline: 1.4540x; 1.4540x over previous
#include <cuda_runtime.h>
#include <cuda_fp16.h>

#define BSZ 8
#define LEN 2048
#define HID 1024
#define NH  16
#define HD  64
#define MTOT (BSZ*LEN)      /* 16384 */
#define NKV  (NH*HD)        /* 1024  */
#define MARGIN 1.5e-3f

#define BM 128
#define BN 128
#define BK 32
#define NITER (HID/BK)          /* 32 */
#define STAGES 2
#define STAGE_BYTES 24576       /* A 8KB + Bhi 8KB + Bmid 8KB */

// ---------------- scratch (device globals; allocation-free rule) ------------
__device__ float g_V1[(size_t)MTOT * NKV];
__device__ __half g_Ah[(size_t)MTOT * HID];
__device__ __half g_WhiV[(size_t)NKV * HID];   // [n][k] K-major
__device__ __half g_WmidV[(size_t)NKV * HID];
__device__ __half g_WhiK[(size_t)NKV * HID];
__device__ __half g_WmidK[(size_t)NKV * HID];
__device__ unsigned char g_valid[MTOT * NH];
__device__ int2 g_fm[MTOT * NH];
__device__ int2 g_bm[MTOT * NH];
__device__ int g_fixcnt;
__device__ int g_fixlist[MTOT * NH];

// SW64 swizzle for 64-byte rows (4x 16B chunks): chunk ^= (row>>1)&3
#define SWZ64(row, chunk) ((row) * 64 + (((chunk) ^ (((row) >> 1) & 3)) << 4))

__device__ __forceinline__ unsigned smem_u32(const void* p) {
    unsigned a;
    asm("{ .reg .u64 t; cvta.to.shared.u64 t, %1; cvt.u32.u64 %0, t; }" : "=r"(a) : "l"(p));
    return a;
}
#define LDSM_X4(r0, r1, r2, r3, addr) \
    asm volatile("ldmatrix.sync.aligned.m8n8.x4.shared.b16 {%0,%1,%2,%3},[%4];" \
        : "=r"(r0), "=r"(r1), "=r"(r2), "=r"(r3) : "r"(addr))
#define MMA16816(c, a0, a1, a2, a3, b0, b1) \
    asm volatile("mma.sync.aligned.m16n8k16.row.col.f32.f16.f16.f32 " \
        "{%0,%1,%2,%3},{%4,%5,%6,%7},{%8,%9},{%0,%1,%2,%3};" \
        : "+f"((c)[0]), "+f"((c)[1]), "+f"((c)[2]), "+f"((c)[3]) \
        : "r"(a0), "r"(a1), "r"(a2), "r"(a3), "r"(b0), "r"(b1))
#define CP_ASYNC16(dst, src) \
    asm volatile("cp.async.cg.shared.global [%0], [%1], 16;" :: "r"(dst), "l"(src))
#define CP_COMMIT() asm volatile("cp.async.commit_group;")
#define CP_WAIT1()  asm volatile("cp.async.wait_group 1;")

// ---------------------------------------------------------------------------
// A: f32 -> f16 (no residual); also zero the fixup counter
__global__ void convA_kernel(const float* __restrict__ hs)
{
    if (blockIdx.x == 0 && threadIdx.x == 0) g_fixcnt = 0;
    const size_t t = (size_t)blockIdx.x * blockDim.x + threadIdx.x;
    const size_t o = t * 8;
    float4 x0 = *(const float4*)(hs + o);
    float4 x1 = *(const float4*)(hs + o + 4);
    float xs[8] = {x0.x, x0.y, x0.z, x0.w, x1.x, x1.y, x1.z, x1.w};
    union { __half b[8]; uint4 u; } h;
    #pragma unroll
    for (int i = 0; i < 8; i++) h.b[i] = __float2half_rn(xs[i]);
    *(uint4*)(g_Ah + o) = h.u;
}

// transpose + split weights: W[k][n] f32 -> out[n][k] f16 hi/mid
__global__ void splitW_kernel(const float* __restrict__ Wv, const float* __restrict__ Wk)
{
    __shared__ float s[32][33];
    const float* W = blockIdx.z ? Wk : Wv;
    __half* Ohi  = blockIdx.z ? g_WhiK  : g_WhiV;
    __half* Omid = blockIdx.z ? g_WmidK : g_WmidV;
    const int kb = blockIdx.x * 32, nb = blockIdx.y * 32;
    const int c = threadIdx.x & 31, r0 = threadIdx.x >> 5;
    #pragma unroll
    for (int j = 0; j < 4; j++) {
        int r = r0 + j * 8;
        s[r][c] = W[(size_t)(kb + r) * NKV + nb + c];
    }
    __syncthreads();
    #pragma unroll
    for (int j = 0; j < 4; j++) {
        int r = r0 + j * 8;
        float x = s[c][r];
        __half hb = __float2half_rn(x);
        Ohi [(size_t)(nb + r) * HID + kb + c] = hb;
        Omid[(size_t)(nb + r) * HID + kb + c] = __float2half_rn(x - __half2float(hb));
    }
}

// ---------------------------------------------------------------------------
// HMMA GEMM, fp16 2-product (A_h@Whi + A_h@Wmid), cp.async 2-stage, A reused.
//   grid.x 0..7 : V path      grid.x 8..15 : K path (fused dots)
// ---------------------------------------------------------------------------
__global__ __launch_bounds__(256, 2)
void mma_kernel(const float* __restrict__ biasV, const float* __restrict__ biasK,
                const float* __restrict__ RH)
{
    __shared__ __align__(1024) unsigned char smem_buf[STAGES * STAGE_BYTES];
    const unsigned sBase = smem_u32(smem_buf);

    const int tid = threadIdx.x;
    const int lane = tid & 31, wid = tid >> 5;
    const int warpM = wid & 1, warpN = wid >> 1;      // 2 x 4 warps, tile 64x32
    const int z  = blockIdx.x >> 3;
    const int n0 = (blockIdx.x & 7) * BN;
    const int m0 = blockIdx.y * BM;

    const __half* Whi  = z ? g_WhiK  : g_WhiV;
    const __half* Wmid = z ? g_WmidK : g_WmidV;

    // loader mapping: thread t -> rows (t>>2, t>>2+64), chunk t&3
    const int lr = tid >> 2;
    const int lc = tid & 3;
    const unsigned d0 = SWZ64(lr, lc);
    const unsigned d1 = SWZ64(lr + 64, lc);
    const size_t gA0 = (size_t)(m0 + lr) * (HID * 2) + lc * 16;
    const size_t gA1 = (size_t)(m0 + lr + 64) * (HID * 2) + lc * 16;
    const size_t gB0 = (size_t)(n0 + lr) * (HID * 2) + lc * 16;
    const size_t gB1 = (size_t)(n0 + lr + 64) * (HID * 2) + lc * 16;

    float acc[4][4][4];
    #pragma unroll
    for (int i = 0; i < 4; i++)
        #pragma unroll
        for (int j = 0; j < 4; j++)
            #pragma unroll
            for (int q = 0; q < 4; q++) acc[i][j][q] = 0.f;

    auto issue = [&](int it) {
        const char* aS = (const char*)g_Ah + it * 64;
        const char* bh = (const char*)Whi + it * 64;
        const char* bm = (const char*)Wmid + it * 64;
        const unsigned st = sBase + (it & 1) * STAGE_BYTES;
        CP_ASYNC16(st + d0, aS + gA0);
        CP_ASYNC16(st + d1, aS + gA1);
        CP_ASYNC16(st + 8192 + d0, bh + gB0);
        CP_ASYNC16(st + 8192 + d1, bh + gB1);
        CP_ASYNC16(st + 16384 + d0, bm + gB0);
        CP_ASYNC16(st + 16384 + d1, bm + gB1);
    };

    issue(0); CP_COMMIT();
    issue(1); CP_COMMIT();

    // ldsm base addresses (stage 0, ks 0)
    const int aRowBase = warpM * 64 + (lane & 15);
    const int bRowBase = warpN * 32 + (lane & 15);
    const int khalf = lane >> 4;
    unsigned aAd[4], bhAd[2], bmAd[2];
    #pragma unroll
    for (int mf = 0; mf < 4; mf++) aAd[mf] = sBase + SWZ64(aRowBase + mf * 16, khalf);
    #pragma unroll
    for (int nb = 0; nb < 2; nb++) {
        bhAd[nb] = sBase + 8192  + SWZ64(bRowBase + nb * 16, khalf);
        bmAd[nb] = sBase + 16384 + SWZ64(bRowBase + nb * 16, khalf);
    }

    for (int it = 0; it < NITER; it++) {
        CP_WAIT1();
        __syncthreads();
        const unsigned so = (it & 1) * STAGE_BYTES;
        #pragma unroll
        for (int ks = 0; ks < 2; ks++) {
            const unsigned sx = so ^ (ks ? 0x20u : 0u);   // ks=1: chunk+2 == XOR 0x20
            unsigned af[4][4], bh[2][4], bm[2][4];
            #pragma unroll
            for (int mf = 0; mf < 4; mf++)
                LDSM_X4(af[mf][0], af[mf][1], af[mf][2], af[mf][3], (aAd[mf] + so) ^ (sx ^ so));
            #pragma unroll
            for (int nb = 0; nb < 2; nb++) {
                LDSM_X4(bh[nb][0], bh[nb][1], bh[nb][2], bh[nb][3], (bhAd[nb] + so) ^ (sx ^ so));
                LDSM_X4(bm[nb][0], bm[nb][1], bm[nb][2], bm[nb][3], (bmAd[nb] + so) ^ (sx ^ so));
            }
            #pragma unroll
            for (int mf = 0; mf < 4; mf++)
                #pragma unroll
                for (int nf = 0; nf < 4; nf++) {
                    unsigned h0 = bh[nf >> 1][(nf & 1) ? 1 : 0];
                    unsigned h1 = bh[nf >> 1][(nf & 1) ? 3 : 2];
                    MMA16816(acc[mf][nf], af[mf][0], af[mf][1], af[mf][2], af[mf][3], h0, h1);
                    unsigned m0r = bm[nf >> 1][(nf & 1) ? 1 : 0];
                    unsigned m1r = bm[nf >> 1][(nf & 1) ? 3 : 2];
                    MMA16816(acc[mf][nf], af[mf][0], af[mf][1], af[mf][2], af[mf][3], m0r, m1r);
                }
        }
        __syncthreads();
        if (it + 2 < NITER) issue(it + 2);
        CP_COMMIT();
    }

    // ---------------- epilogue ----------------
    const int rBase = m0 + warpM * 64 + (lane >> 2);
    const int cBase = n0 + warpN * 32 + (lane & 3) * 2;

    if (z == 0) {
        #pragma unroll
        for (int mf = 0; mf < 4; mf++) {
            #pragma unroll
            for (int nf = 0; nf < 4; nf++) {
                int col = cBase + nf * 8;
                float b0 = biasV[col], b1 = biasV[col + 1];
                int r0 = rBase + mf * 16;
                float2 v;
                v.x = fmaxf(acc[mf][nf][0] + b0, 0.f);
                v.y = fmaxf(acc[mf][nf][1] + b1, 0.f);
                *(float2*)(g_V1 + (size_t)r0 * NKV + col) = v;
                v.x = fmaxf(acc[mf][nf][2] + b0, 0.f);
                v.y = fmaxf(acc[mf][nf][3] + b1, 0.f);
                *(float2*)(g_V1 + (size_t)(r0 + 8) * NKV + col) = v;
            }
        }
    } else {
        __syncthreads();
        float* sdots = (float*)smem_buf;       // [128][2]
        if (tid < 256) sdots[tid] = 0.f;
        __syncthreads();
        const int hloc = warpN >> 1;
        #pragma unroll
        for (int mf = 0; mf < 4; mf++) {
            float slo = 0.f, shi = 0.f;
            #pragma unroll
            for (int nf = 0; nf < 4; nf++) {
                int col = cBase + nf * 8;
                float b0 = biasK[col], b1 = biasK[col + 1];
                float w0 = RH[col],   w1 = RH[col + 1];
                slo += fmaxf(acc[mf][nf][0] + b0, 0.f) * w0
                     + fmaxf(acc[mf][nf][1] + b1, 0.f) * w1;
                shi += fmaxf(acc[mf][nf][2] + b0, 0.f) * w0
                     + fmaxf(acc[mf][nf][3] + b1, 0.f) * w1;
            }
            slo += __shfl_xor_sync(0xffffffffu, slo, 1);
            slo += __shfl_xor_sync(0xffffffffu, slo, 2);
            shi += __shfl_xor_sync(0xffffffffu, shi, 1);
            shi += __shfl_xor_sync(0xffffffffu, shi, 2);
            if ((lane & 3) == 0) {
                int rloc = warpM * 64 + mf * 16 + (lane >> 2);
                atomicAdd(&sdots[rloc * 2 + hloc], slo);
                atomicAdd(&sdots[(rloc + 8) * 2 + hloc], shi);
            }
        }
        __syncthreads();
        if (tid < 256) {
            int rloc = tid >> 1, h = tid & 1;
            int m = m0 + rloc;
            int n = (n0 >> 6) + h;
            float dd = sdots[tid];
            int o = m * NH + n;
            if (fabsf(dd - 0.5f) < MARGIN) {
                int ix = atomicAdd(&g_fixcnt, 1);
                g_fixlist[ix] = (m << 4) | n;
                g_valid[o] = 0;
            } else {
                g_valid[o] = (dd > 0.5f) ? 1 : 0;
            }
        }
    }
}

// ---------------------------------------------------------------------------
// exact fp32 recompute near threshold: one warp per item
// ---------------------------------------------------------------------------
__global__ void fix_kernel(const float* __restrict__ hs, const float* __restrict__ K1w,
                           const float* __restrict__ K1b, const float* __restrict__ RH)
{
    const int cnt = g_fixcnt;
    const int w = blockIdx.x * (blockDim.x >> 5) + (threadIdx.x >> 5);
    const int lane = threadIdx.x & 31;
    const int nw = gridDim.x * (blockDim.x >> 5);
    for (int i = w; i < cnt; i += nw) {
        int mn = g_fixlist[i];
        int m = mn >> 4, n = mn & 15;
        const float* a  = hs + (size_t)m * HID;
        const float* wp = K1w + n * HD + lane;
        float a0 = 0.f, a1 = 0.f;
        #pragma unroll 4
        for (int k = 0; k < HID; k++) {
            float av = __ldg(a + k);
            a0 = fmaf(av, __ldg(wp + (size_t)k * NKV), a0);
            a1 = fmaf(av, __ldg(wp + (size_t)k * NKV + 32), a1);
        }
        float d = fmaxf(a0 + K1b[n * HD + lane], 0.f) * RH[n * HD + lane]
                + fmaxf(a1 + K1b[n * HD + lane + 32], 0.f) * RH[n * HD + lane + 32];
        #pragma unroll
        for (int o = 16; o; o >>= 1) d += __shfl_xor_sync(0xffffffffu, d, o);
        if (lane == 0) g_valid[m * NH + n] = (d > 0.5f) ? 1 : 0;
    }
}

// ---------------------------------------------------------------------------
// parallel scan via prefix/suffix max. Semantics identical to reference:
//  fa = prefix-max over j in [1,l] of (valid[j]? j:0); fb = pmax[fa-1] (0 if fa==0)
//  ba: suffix-max over j in [l,L-2] of (valid[j]? L-1-j:0); 0 -> L-1
//  bb = smax[(L-1-ba)+1], 0 -> L-1
// ---------------------------------------------------------------------------
__global__ __launch_bounds__(256)
void scan_kernel()
{
    __shared__ int pm[LEN];
    __shared__ int sx[LEN];
    __shared__ int tpart[256];
    const int b = blockIdx.x >> 4;
    const int n = blockIdx.x & 15;
    const int tid = threadIdx.x;

    unsigned char v8[8];
    #pragma unroll
    for (int j = 0; j < 8; j++)
        v8[j] = g_valid[(size_t)(b * LEN + tid * 8 + j) * NH + n];

    // forward prefix max
    {
        int run = 0, loc[8];
        #pragma unroll
        for (int j = 0; j < 8; j++) {
            int l = tid * 8 + j;
            int a = (v8[j] && l >= 1) ? l : 0;
            run = max(run, a);
            loc[j] = run;
        }
        tpart[tid] = run;
        __syncthreads();
        int acc = tpart[tid];
        #pragma unroll
        for (int of = 1; of < 256; of <<= 1) {
            int o = (tid >= of) ? tpart[tid - of] : 0;
            __syncthreads();
            acc = max(acc, o);
            tpart[tid] = acc;
            __syncthreads();
        }
        int pre = (tid > 0) ? tpart[tid - 1] : 0;
        #pragma unroll
        for (int j = 0; j < 8; j++) pm[tid * 8 + j] = max(pre, loc[j]);
    }
    __syncthreads();
    // backward suffix max (values L-1-l, positions l<=L-2)
    {
        int run = 0, loc[8];
        #pragma unroll
        for (int j = 7; j >= 0; j--) {
            int l = tid * 8 + j;
            int a = (v8[j] && l <= LEN - 2) ? (LEN - 1 - l) : 0;
            run = max(run, a);
            loc[j] = run;
        }
        tpart[tid] = run;
        __syncthreads();
        int acc = tpart[tid];
        #pragma unroll
        for (int of = 1; of < 256; of <<= 1) {
            int o = (tid + of < 256) ? tpart[tid + of] : 0;
            __syncthreads();
            acc = max(acc, o);
            tpart[tid] = acc;
            __syncthreads();
        }
        int suf = (tid < 255) ? tpart[tid + 1] : 0;
        #pragma unroll
        for (int j = 0; j < 8; j++) sx[tid * 8 + j] = max(suf, loc[j]);
    }
    __syncthreads();

    #pragma unroll
    for (int j = 0; j < 8; j++) {
        int l = tid * 8 + j;
        const size_t o = (size_t)(b * LEN + l) * NH + n;
        int fa = pm[l];
        int fb = (fa > 0) ? pm[fa - 1] : 0;
        g_fm[o] = make_int2(fa, fb);
        int s = sx[l];
        int ba, bb;
        if (s == 0) { ba = LEN - 1; bb = LEN - 1; }
        else {
            ba = s;
            int l2 = (LEN - 1) - s;
            int s2 = (l2 + 1 <= LEN - 1) ? sx[l2 + 1] : 0;
            bb = (s2 == 0) ? (LEN - 1) : s2;
        }
        g_bm[o] = make_int2(ba, bb);
    }
}

// ---------------------------------------------------------------------------
__global__ void gather_kernel(const float* __restrict__ bw, float* __restrict__ out)
{
    const int t = blockIdx.x * blockDim.x + threadIdx.x;
    const int h4 = t & 15;
    const int n  = (t >> 4) & 15;
    const int m  = t >> 8;
    if (m >= MTOT) return;
    const int b = m >> 11;
    const size_t io = (size_t)m * NH + n;
    const int2 f  = g_fm[io];
    const int2 bk = g_bm[io];
    const float4 w = *(const float4*)(bw + n * 4);
    const int base = b * LEN;
    const int col = n * HD + h4 * 4;
    const float4 v0 = *(const float4*)(g_V1 + (size_t)(base + f.x)  * NKV + col);
    const float4 v1 = *(const float4*)(g_V1 + (size_t)(base + f.y)  * NKV + col);
    const float4 v2 = *(const float4*)(g_V1 + (size_t)(base + bk.x) * NKV + col);
    const float4 v3 = *(const float4*)(g_V1 + (size_t)(base + bk.y) * NKV + col);
    float4 rr;
    rr.x = w.x * v0.x + w.y * v1.x + w.z * v2.x + w.w * v3.x;
    rr.y = w.x * v0.y + w.y * v1.y + w.z * v2.y + w.w * v3.y;
    rr.z = w.x * v0.z + w.y * v1.z + w.z * v2.z + w.w * v3.z;
    rr.w = w.x * v0.w + w.y * v1.w + w.z * v2.w + w.w * v3.w;
    *(float4*)(out + (size_t)m * NKV + col) = rr;
}

// ---------------------------------------------------------------------------
extern "C" void kernel_launch(void* const* d_in, const int* in_sizes, int n_in,
                              void* d_out, int out_size)
{
    const float* hs  = (const float*)d_in[0];
    const float* K1w = (const float*)d_in[1];
    const float* K1b = (const float*)d_in[2];
    const float* V1w = (const float*)d_in[3];
    const float* V1b = (const float*)d_in[4];
    const float* bw  = (const float*)d_in[5];
    const float* RH  = (const float*)d_in[6];
    float* out = (float*)d_out;

    convA_kernel<<<(MTOT * HID / 8) / 256, 256>>>(hs);
    splitW_kernel<<<dim3(32, 32, 2), 256>>>(V1w, K1w);
    mma_kernel<<<dim3(16, MTOT / BM), 256>>>(V1b, K1b, RH);
    fix_kernel<<<256, 256>>>(hs, K1w, K1b, RH);
    scan_kernel<<<BSZ * NH, 256>>>();
    gather_kernel<<<(MTOT * NH * 16) / 256, 256>>>(bw, out);
}

// round 6
// speedup vs baseline: 2.1148x; 1.4545x over previous
#include <cuda_runtime.h>
#include <cuda_fp16.h>

#define BSZ 8
#define LEN 2048
#define HID 1024
#define NH  16
#define HD  64
#define MTOT (BSZ*LEN)      /* 16384 */
#define NKV  (NH*HD)        /* 1024  */
#define MARGIN 1.5e-3f

#define BM 128
#define BN 128
#define BK 32
#define NITER (HID/BK)          /* 32 */
#define STAGES 2
#define STAGE_BYTES 24576       /* A 8KB + Bhi 8KB + Bmid 8KB */

// ---------------- scratch (device globals; allocation-free rule) ------------
__device__ float g_V1[(size_t)MTOT * NKV];
__device__ __half g_Ah[(size_t)MTOT * HID];
__device__ __half g_WhiV[(size_t)NKV * HID];   // [n][k] K-major
__device__ __half g_WmidV[(size_t)NKV * HID];
__device__ __half g_WhiK[(size_t)NKV * HID];
__device__ __half g_WmidK[(size_t)NKV * HID];
__device__ unsigned char g_valid[MTOT * NH];
__device__ int2 g_fm[MTOT * NH];
__device__ int2 g_bm[MTOT * NH];
__device__ int g_fixcnt;
__device__ int g_fixlist[MTOT * NH];

// SW64 swizzle for 64-byte rows (4x 16B chunks): chunk ^= (row>>1)&3
#define SWZ64(row, chunk) ((row) * 64 + (((chunk) ^ (((row) >> 1) & 3)) << 4))

__device__ __forceinline__ unsigned smem_u32(const void* p) {
    unsigned a;
    asm("{ .reg .u64 t; cvta.to.shared.u64 t, %1; cvt.u32.u64 %0, t; }" : "=r"(a) : "l"(p));
    return a;
}
#define LDSM_X4(r0, r1, r2, r3, addr) \
    asm volatile("ldmatrix.sync.aligned.m8n8.x4.shared.b16 {%0,%1,%2,%3},[%4];" \
        : "=r"(r0), "=r"(r1), "=r"(r2), "=r"(r3) : "r"(addr))
#define MMA16816(c, a0, a1, a2, a3, b0, b1) \
    asm volatile("mma.sync.aligned.m16n8k16.row.col.f32.f16.f16.f32 " \
        "{%0,%1,%2,%3},{%4,%5,%6,%7},{%8,%9},{%0,%1,%2,%3};" \
        : "+f"((c)[0]), "+f"((c)[1]), "+f"((c)[2]), "+f"((c)[3]) \
        : "r"(a0), "r"(a1), "r"(a2), "r"(a3), "r"(b0), "r"(b1))
#define CP_ASYNC16(dst, src) \
    asm volatile("cp.async.cg.shared.global [%0], [%1], 16;" :: "r"(dst), "l"(src))
#define CP_COMMIT() asm volatile("cp.async.commit_group;")
#define CP_WAIT1()  asm volatile("cp.async.wait_group 1;")

// ---------------------------------------------------------------------------
// A: f32 -> f16 (no residual); also zero the fixup counter
__global__ void convA_kernel(const float* __restrict__ hs)
{
    if (blockIdx.x == 0 && threadIdx.x == 0) g_fixcnt = 0;
    const size_t t = (size_t)blockIdx.x * blockDim.x + threadIdx.x;
    const size_t o = t * 8;
    float4 x0 = *(const float4*)(hs + o);
    float4 x1 = *(const float4*)(hs + o + 4);
    float xs[8] = {x0.x, x0.y, x0.z, x0.w, x1.x, x1.y, x1.z, x1.w};
    union { __half b[8]; uint4 u; } h;
    #pragma unroll
    for (int i = 0; i < 8; i++) h.b[i] = __float2half_rn(xs[i]);
    *(uint4*)(g_Ah + o) = h.u;
}

// transpose + split weights: W[k][n] f32 -> out[n][k] f16 hi/mid
__global__ void splitW_kernel(const float* __restrict__ Wv, const float* __restrict__ Wk)
{
    __shared__ float s[32][33];
    const float* W = blockIdx.z ? Wk : Wv;
    __half* Ohi  = blockIdx.z ? g_WhiK  : g_WhiV;
    __half* Omid = blockIdx.z ? g_WmidK : g_WmidV;
    const int kb = blockIdx.x * 32, nb = blockIdx.y * 32;
    const int c = threadIdx.x & 31, r0 = threadIdx.x >> 5;
    #pragma unroll
    for (int j = 0; j < 4; j++) {
        int r = r0 + j * 8;
        s[r][c] = W[(size_t)(kb + r) * NKV + nb + c];
    }
    __syncthreads();
    #pragma unroll
    for (int j = 0; j < 4; j++) {
        int r = r0 + j * 8;
        float x = s[c][r];
        __half hb = __float2half_rn(x);
        Ohi [(size_t)(nb + r) * HID + kb + c] = hb;
        Omid[(size_t)(nb + r) * HID + kb + c] = __float2half_rn(x - __half2float(hb));
    }
}

// ---------------------------------------------------------------------------
// HMMA GEMM, fp16 2-product (A_h@Whi + A_h@Wmid), cp.async 2-stage, A reused.
//   grid.x 0..7 : V path      grid.x 8..15 : K path (fused dots)
// ---------------------------------------------------------------------------
__global__ __launch_bounds__(256, 2)
void mma_kernel(const float* __restrict__ biasV, const float* __restrict__ biasK,
                const float* __restrict__ RH)
{
    __shared__ __align__(1024) unsigned char smem_buf[STAGES * STAGE_BYTES];
    const unsigned sBase = smem_u32(smem_buf);

    const int tid = threadIdx.x;
    const int lane = tid & 31, wid = tid >> 5;
    const int warpM = wid & 1, warpN = wid >> 1;      // 2 x 4 warps, tile 64x32
    const int z  = blockIdx.x >> 3;
    const int n0 = (blockIdx.x & 7) * BN;
    const int m0 = blockIdx.y * BM;

    const __half* Whi  = z ? g_WhiK  : g_WhiV;
    const __half* Wmid = z ? g_WmidK : g_WmidV;

    // loader mapping: thread t -> rows (t>>2, t>>2+64), chunk t&3
    const int lr = tid >> 2;
    const int lc = tid & 3;
    const unsigned d0 = SWZ64(lr, lc);
    const unsigned d1 = SWZ64(lr + 64, lc);
    const size_t gA0 = (size_t)(m0 + lr) * (HID * 2) + lc * 16;
    const size_t gA1 = (size_t)(m0 + lr + 64) * (HID * 2) + lc * 16;
    const size_t gB0 = (size_t)(n0 + lr) * (HID * 2) + lc * 16;
    const size_t gB1 = (size_t)(n0 + lr + 64) * (HID * 2) + lc * 16;

    float acc[4][4][4];
    #pragma unroll
    for (int i = 0; i < 4; i++)
        #pragma unroll
        for (int j = 0; j < 4; j++)
            #pragma unroll
            for (int q = 0; q < 4; q++) acc[i][j][q] = 0.f;

    auto issue = [&](int it) {
        const char* aS = (const char*)g_Ah + it * 64;
        const char* bh = (const char*)Whi + it * 64;
        const char* bm = (const char*)Wmid + it * 64;
        const unsigned st = sBase + (it & 1) * STAGE_BYTES;
        CP_ASYNC16(st + d0, aS + gA0);
        CP_ASYNC16(st + d1, aS + gA1);
        CP_ASYNC16(st + 8192 + d0, bh + gB0);
        CP_ASYNC16(st + 8192 + d1, bh + gB1);
        CP_ASYNC16(st + 16384 + d0, bm + gB0);
        CP_ASYNC16(st + 16384 + d1, bm + gB1);
    };

    issue(0); CP_COMMIT();
    issue(1); CP_COMMIT();

    // ldsm base addresses (stage 0, ks 0)
    const int aRowBase = warpM * 64 + (lane & 15);
    const int bRowBase = warpN * 32 + (lane & 15);
    const int khalf = lane >> 4;
    unsigned aAd[4], bhAd[2], bmAd[2];
    #pragma unroll
    for (int mf = 0; mf < 4; mf++) aAd[mf] = sBase + SWZ64(aRowBase + mf * 16, khalf);
    #pragma unroll
    for (int nb = 0; nb < 2; nb++) {
        bhAd[nb] = sBase + 8192  + SWZ64(bRowBase + nb * 16, khalf);
        bmAd[nb] = sBase + 16384 + SWZ64(bRowBase + nb * 16, khalf);
    }

    for (int it = 0; it < NITER; it++) {
        CP_WAIT1();
        __syncthreads();
        const unsigned so = (it & 1) * STAGE_BYTES;
        #pragma unroll
        for (int ks = 0; ks < 2; ks++) {
            const unsigned sx = so ^ (ks ? 0x20u : 0u);   // ks=1: chunk+2 == XOR 0x20
            unsigned af[4][4], bh[2][4], bm[2][4];
            #pragma unroll
            for (int mf = 0; mf < 4; mf++)
                LDSM_X4(af[mf][0], af[mf][1], af[mf][2], af[mf][3], (aAd[mf] + so) ^ (sx ^ so));
            #pragma unroll
            for (int nb = 0; nb < 2; nb++) {
                LDSM_X4(bh[nb][0], bh[nb][1], bh[nb][2], bh[nb][3], (bhAd[nb] + so) ^ (sx ^ so));
                LDSM_X4(bm[nb][0], bm[nb][1], bm[nb][2], bm[nb][3], (bmAd[nb] + so) ^ (sx ^ so));
            }
            #pragma unroll
            for (int mf = 0; mf < 4; mf++)
                #pragma unroll
                for (int nf = 0; nf < 4; nf++) {
                    unsigned h0 = bh[nf >> 1][(nf & 1) ? 1 : 0];
                    unsigned h1 = bh[nf >> 1][(nf & 1) ? 3 : 2];
                    MMA16816(acc[mf][nf], af[mf][0], af[mf][1], af[mf][2], af[mf][3], h0, h1);
                    unsigned m0r = bm[nf >> 1][(nf & 1) ? 1 : 0];
                    unsigned m1r = bm[nf >> 1][(nf & 1) ? 3 : 2];
                    MMA16816(acc[mf][nf], af[mf][0], af[mf][1], af[mf][2], af[mf][3], m0r, m1r);
                }
        }
        __syncthreads();
        if (it + 2 < NITER) issue(it + 2);
        CP_COMMIT();
    }

    // ---------------- epilogue ----------------
    const int rBase = m0 + warpM * 64 + (lane >> 2);
    const int cBase = n0 + warpN * 32 + (lane & 3) * 2;

    if (z == 0) {
        #pragma unroll
        for (int mf = 0; mf < 4; mf++) {
            #pragma unroll
            for (int nf = 0; nf < 4; nf++) {
                int col = cBase + nf * 8;
                float b0 = biasV[col], b1 = biasV[col + 1];
                int r0 = rBase + mf * 16;
                float2 v;
                v.x = fmaxf(acc[mf][nf][0] + b0, 0.f);
                v.y = fmaxf(acc[mf][nf][1] + b1, 0.f);
                *(float2*)(g_V1 + (size_t)r0 * NKV + col) = v;
                v.x = fmaxf(acc[mf][nf][2] + b0, 0.f);
                v.y = fmaxf(acc[mf][nf][3] + b1, 0.f);
                *(float2*)(g_V1 + (size_t)(r0 + 8) * NKV + col) = v;
            }
        }
    } else {
        __syncthreads();
        float* sdots = (float*)smem_buf;       // [128][2]
        if (tid < 256) sdots[tid] = 0.f;
        __syncthreads();
        const int hloc = warpN >> 1;
        #pragma unroll
        for (int mf = 0; mf < 4; mf++) {
            float slo = 0.f, shi = 0.f;
            #pragma unroll
            for (int nf = 0; nf < 4; nf++) {
                int col = cBase + nf * 8;
                float b0 = biasK[col], b1 = biasK[col + 1];
                float w0 = RH[col],   w1 = RH[col + 1];
                slo += fmaxf(acc[mf][nf][0] + b0, 0.f) * w0
                     + fmaxf(acc[mf][nf][1] + b1, 0.f) * w1;
                shi += fmaxf(acc[mf][nf][2] + b0, 0.f) * w0
                     + fmaxf(acc[mf][nf][3] + b1, 0.f) * w1;
            }
            slo += __shfl_xor_sync(0xffffffffu, slo, 1);
            slo += __shfl_xor_sync(0xffffffffu, slo, 2);
            shi += __shfl_xor_sync(0xffffffffu, shi, 1);
            shi += __shfl_xor_sync(0xffffffffu, shi, 2);
            if ((lane & 3) == 0) {
                int rloc = warpM * 64 + mf * 16 + (lane >> 2);
                atomicAdd(&sdots[rloc * 2 + hloc], slo);
                atomicAdd(&sdots[(rloc + 8) * 2 + hloc], shi);
            }
        }
        __syncthreads();
        if (tid < 256) {
            int rloc = tid >> 1, h = tid & 1;
            int m = m0 + rloc;
            int n = (n0 >> 6) + h;
            float dd = sdots[tid];
            int o = m * NH + n;
            if (fabsf(dd - 0.5f) < MARGIN) {
                int ix = atomicAdd(&g_fixcnt, 1);
                g_fixlist[ix] = (m << 4) | n;
                g_valid[o] = 0;
            } else {
                g_valid[o] = (dd > 0.5f) ? 1 : 0;
            }
        }
    }
}

// ---------------------------------------------------------------------------
// exact fp32 recompute near threshold: one BLOCK per item, k-parallel.
// 8 warps x 128-k-slice, lanes cover 64 columns (coalesced W rows).
// ---------------------------------------------------------------------------
__global__ __launch_bounds__(256)
void fix_kernel(const float* __restrict__ hs, const float* __restrict__ K1w,
                const float* __restrict__ K1b, const float* __restrict__ RH)
{
    __shared__ float sA[8][64];
    const int cnt = g_fixcnt;
    const int tid = threadIdx.x;
    const int lane = tid & 31, wg = tid >> 5;
    for (int i = blockIdx.x; i < cnt; i += gridDim.x) {
        const int mn = g_fixlist[i];
        const int m = mn >> 4, n = mn & 15;
        const float* a  = hs + (size_t)m * HID + wg * 128;
        const float* wp = K1w + (size_t)(wg * 128) * NKV + n * HD + lane;
        float a0 = 0.f, a1 = 0.f;
        #pragma unroll 8
        for (int k = 0; k < 128; k++) {
            float av = a[k];
            a0 = fmaf(av, wp[(size_t)k * NKV], a0);
            a1 = fmaf(av, wp[(size_t)k * NKV + 32], a1);
        }
        sA[wg][lane]      = a0;
        sA[wg][lane + 32] = a1;
        __syncthreads();
        if (tid < 64) {
            float s = 0.f;
            #pragma unroll
            for (int w = 0; w < 8; w++) s += sA[w][tid];
            s = fmaxf(s + K1b[n * HD + tid], 0.f) * RH[n * HD + tid];
            sA[0][tid] = s;
        }
        __syncthreads();
        if (tid == 0) {
            float d = 0.f;
            #pragma unroll
            for (int c = 0; c < 64; c++) d += sA[0][c];
            g_valid[m * NH + n] = (d > 0.5f) ? 1 : 0;
        }
        __syncthreads();
    }
}

// ---------------------------------------------------------------------------
// parallel scan via prefix/suffix max (exact reference semantics)
// ---------------------------------------------------------------------------
__global__ __launch_bounds__(256)
void scan_kernel()
{
    __shared__ int pm[LEN];
    __shared__ int sx[LEN];
    __shared__ int tpart[256];
    const int b = blockIdx.x >> 4;
    const int n = blockIdx.x & 15;
    const int tid = threadIdx.x;

    unsigned char v8[8];
    #pragma unroll
    for (int j = 0; j < 8; j++)
        v8[j] = g_valid[(size_t)(b * LEN + tid * 8 + j) * NH + n];

    // forward prefix max
    {
        int run = 0, loc[8];
        #pragma unroll
        for (int j = 0; j < 8; j++) {
            int l = tid * 8 + j;
            int a = (v8[j] && l >= 1) ? l : 0;
            run = max(run, a);
            loc[j] = run;
        }
        tpart[tid] = run;
        __syncthreads();
        int acc = tpart[tid];
        #pragma unroll
        for (int of = 1; of < 256; of <<= 1) {
            int o = (tid >= of) ? tpart[tid - of] : 0;
            __syncthreads();
            acc = max(acc, o);
            tpart[tid] = acc;
            __syncthreads();
        }
        int pre = (tid > 0) ? tpart[tid - 1] : 0;
        #pragma unroll
        for (int j = 0; j < 8; j++) pm[tid * 8 + j] = max(pre, loc[j]);
    }
    __syncthreads();
    // backward suffix max (values L-1-l, positions l<=L-2)
    {
        int run = 0, loc[8];
        #pragma unroll
        for (int j = 7; j >= 0; j--) {
            int l = tid * 8 + j;
            int a = (v8[j] && l <= LEN - 2) ? (LEN - 1 - l) : 0;
            run = max(run, a);
            loc[j] = run;
        }
        tpart[tid] = run;
        __syncthreads();
        int acc = tpart[tid];
        #pragma unroll
        for (int of = 1; of < 256; of <<= 1) {
            int o = (tid + of < 256) ? tpart[tid + of] : 0;
            __syncthreads();
            acc = max(acc, o);
            tpart[tid] = acc;
            __syncthreads();
        }
        int suf = (tid < 255) ? tpart[tid + 1] : 0;
        #pragma unroll
        for (int j = 0; j < 8; j++) sx[tid * 8 + j] = max(suf, loc[j]);
    }
    __syncthreads();

    #pragma unroll
    for (int j = 0; j < 8; j++) {
        int l = tid * 8 + j;
        const size_t o = (size_t)(b * LEN + l) * NH + n;
        int fa = pm[l];
        int fb = (fa > 0) ? pm[fa - 1] : 0;
        g_fm[o] = make_int2(fa, fb);
        int s = sx[l];
        int ba, bb;
        if (s == 0) { ba = LEN - 1; bb = LEN - 1; }
        else {
            ba = s;
            int l2 = (LEN - 1) - s;
            int s2 = (l2 + 1 <= LEN - 1) ? sx[l2 + 1] : 0;
            bb = (s2 == 0) ? (LEN - 1) : s2;
        }
        g_bm[o] = make_int2(ba, bb);
    }
}

// ---------------------------------------------------------------------------
__global__ void gather_kernel(const float* __restrict__ bw, float* __restrict__ out)
{
    const int t = blockIdx.x * blockDim.x + threadIdx.x;
    const int h4 = t & 15;
    const int n  = (t >> 4) & 15;
    const int m  = t >> 8;
    if (m >= MTOT) return;
    const int b = m >> 11;
    const size_t io = (size_t)m * NH + n;
    const int2 f  = g_fm[io];
    const int2 bk = g_bm[io];
    const float4 w = *(const float4*)(bw + n * 4);
    const int base = b * LEN;
    const int col = n * HD + h4 * 4;
    const float4 v0 = *(const float4*)(g_V1 + (size_t)(base + f.x)  * NKV + col);
    const float4 v1 = *(const float4*)(g_V1 + (size_t)(base + f.y)  * NKV + col);
    const float4 v2 = *(const float4*)(g_V1 + (size_t)(base + bk.x) * NKV + col);
    const float4 v3 = *(const float4*)(g_V1 + (size_t)(base + bk.y) * NKV + col);
    float4 rr;
    rr.x = w.x * v0.x + w.y * v1.x + w.z * v2.x + w.w * v3.x;
    rr.y = w.x * v0.y + w.y * v1.y + w.z * v2.y + w.w * v3.y;
    rr.z = w.x * v0.z + w.y * v1.z + w.z * v2.z + w.w * v3.z;
    rr.w = w.x * v0.w + w.y * v1.w + w.z * v2.w + w.w * v3.w;
    *(float4*)(out + (size_t)m * NKV + col) = rr;
}

// ---------------------------------------------------------------------------
extern "C" void kernel_launch(void* const* d_in, const int* in_sizes, int n_in,
                              void* d_out, int out_size)
{
    const float* hs  = (const float*)d_in[0];
    const float* K1w = (const float*)d_in[1];
    const float* K1b = (const float*)d_in[2];
    const float* V1w = (const float*)d_in[3];
    const float* V1b = (const float*)d_in[4];
    const float* bw  = (const float*)d_in[5];
    const float* RH  = (const float*)d_in[6];
    float* out = (float*)d_out;

    convA_kernel<<<(MTOT * HID / 8) / 256, 256>>>(hs);
    splitW_kernel<<<dim3(32, 32, 2), 256>>>(V1w, K1w);
    mma_kernel<<<dim3(16, MTOT / BM), 256>>>(V1b, K1b, RH);
    fix_kernel<<<2048, 256>>>(hs, K1w, K1b, RH);
    scan_kernel<<<BSZ * NH, 256>>>();
    gather_kernel<<<(MTOT * NH * 16) / 256, 256>>>(bw, out);
}

// round 7
// speedup vs baseline: 3.2240x; 1.5244x over previous
#include <cuda_runtime.h>
#include <cuda_fp16.h>

#define BSZ 8
#define LEN 2048
#define HID 1024
#define NH  16
#define HD  64
#define MTOT (BSZ*LEN)      /* 16384 */
#define NKV  (NH*HD)        /* 1024  */
#define MARGIN 2e-3f

#define BM 128
#define BN 128
#define BK 32
#define NITER (HID/BK)          /* 32 */
#define STAGES 3
#define STAGE_BYTES 16384       /* A 8KB + B 8KB */

// ---------------- scratch (device globals; allocation-free rule) ------------
__device__ float g_V1[(size_t)MTOT * NKV];
__device__ __half g_Ah[(size_t)MTOT * HID];
__device__ __half g_WhV[(size_t)NKV * HID];   // [n][k] K-major
__device__ __half g_WhK[(size_t)NKV * HID];
__device__ unsigned char g_valid[MTOT * NH];
__device__ int2 g_fm[MTOT * NH];
__device__ int2 g_bm[MTOT * NH];
__device__ int g_fixcnt;
__device__ int g_fixlist[MTOT * NH];

// SW64 swizzle for 64-byte rows (4x 16B chunks): chunk ^= (row>>1)&3
#define SWZ64(row, chunk) ((row) * 64 + (((chunk) ^ (((row) >> 1) & 3)) << 4))

__device__ __forceinline__ unsigned smem_u32(const void* p) {
    unsigned a;
    asm("{ .reg .u64 t; cvta.to.shared.u64 t, %1; cvt.u32.u64 %0, t; }" : "=r"(a) : "l"(p));
    return a;
}
#define LDSM_X4(r0, r1, r2, r3, addr) \
    asm volatile("ldmatrix.sync.aligned.m8n8.x4.shared.b16 {%0,%1,%2,%3},[%4];" \
        : "=r"(r0), "=r"(r1), "=r"(r2), "=r"(r3) : "r"(addr))
#define MMA16816(c, a0, a1, a2, a3, b0, b1) \
    asm volatile("mma.sync.aligned.m16n8k16.row.col.f32.f16.f16.f32 " \
        "{%0,%1,%2,%3},{%4,%5,%6,%7},{%8,%9},{%0,%1,%2,%3};" \
        : "+f"((c)[0]), "+f"((c)[1]), "+f"((c)[2]), "+f"((c)[3]) \
        : "r"(a0), "r"(a1), "r"(a2), "r"(a3), "r"(b0), "r"(b1))
#define CP_ASYNC16(dst, src) \
    asm volatile("cp.async.cg.shared.global [%0], [%1], 16;" :: "r"(dst), "l"(src))
#define CP_COMMIT() asm volatile("cp.async.commit_group;")
#define CP_WAIT1()  asm volatile("cp.async.wait_group 1;")

// ---------------------------------------------------------------------------
// A: f32 -> f16; also zero the fixup counter
__global__ void convA_kernel(const float* __restrict__ hs)
{
    if (blockIdx.x == 0 && threadIdx.x == 0) g_fixcnt = 0;
    const size_t t = (size_t)blockIdx.x * blockDim.x + threadIdx.x;
    const size_t o = t * 8;
    float4 x0 = *(const float4*)(hs + o);
    float4 x1 = *(const float4*)(hs + o + 4);
    float xs[8] = {x0.x, x0.y, x0.z, x0.w, x1.x, x1.y, x1.z, x1.w};
    union { __half b[8]; uint4 u; } h;
    #pragma unroll
    for (int i = 0; i < 8; i++) h.b[i] = __float2half_rn(xs[i]);
    *(uint4*)(g_Ah + o) = h.u;
}

// transpose weights: W[k][n] f32 -> out[n][k] f16
__global__ void convW_kernel(const float* __restrict__ Wv, const float* __restrict__ Wk)
{
    __shared__ float s[32][33];
    const float* W = blockIdx.z ? Wk : Wv;
    __half* O = blockIdx.z ? g_WhK : g_WhV;
    const int kb = blockIdx.x * 32, nb = blockIdx.y * 32;
    const int c = threadIdx.x & 31, r0 = threadIdx.x >> 5;
    #pragma unroll
    for (int j = 0; j < 4; j++) {
        int r = r0 + j * 8;
        s[r][c] = W[(size_t)(kb + r) * NKV + nb + c];
    }
    __syncthreads();
    #pragma unroll
    for (int j = 0; j < 4; j++) {
        int r = r0 + j * 8;
        O[(size_t)(nb + r) * HID + kb + c] = __float2half_rn(s[c][r]);
    }
}

// ---------------------------------------------------------------------------
// HMMA GEMM, fp16 single-product, cp.async 3-stage, one barrier per k-iter.
//   grid.x 0..7 : V path      grid.x 8..15 : K path (fused dots)
// ---------------------------------------------------------------------------
__global__ __launch_bounds__(256, 2)
void mma_kernel(const float* __restrict__ biasV, const float* __restrict__ biasK,
                const float* __restrict__ RH)
{
    __shared__ __align__(1024) unsigned char smem_buf[STAGES * STAGE_BYTES];
    const unsigned sBase = smem_u32(smem_buf);

    const int tid = threadIdx.x;
    const int lane = tid & 31, wid = tid >> 5;
    const int warpM = wid & 1, warpN = wid >> 1;      // 2 x 4 warps, tile 64x32
    const int z  = blockIdx.x >> 3;
    const int n0 = (blockIdx.x & 7) * BN;
    const int m0 = blockIdx.y * BM;

    const __half* Wh = z ? g_WhK : g_WhV;

    // loader mapping: thread t -> rows (t>>2, t>>2+64), chunk t&3
    const int lr = tid >> 2;
    const int lc = tid & 3;
    const unsigned d0 = SWZ64(lr, lc);
    const unsigned d1 = SWZ64(lr + 64, lc);
    const size_t gA0 = (size_t)(m0 + lr) * (HID * 2) + lc * 16;
    const size_t gA1 = (size_t)(m0 + lr + 64) * (HID * 2) + lc * 16;
    const size_t gB0 = (size_t)(n0 + lr) * (HID * 2) + lc * 16;
    const size_t gB1 = (size_t)(n0 + lr + 64) * (HID * 2) + lc * 16;

    float acc[4][4][4];
    #pragma unroll
    for (int i = 0; i < 4; i++)
        #pragma unroll
        for (int j = 0; j < 4; j++)
            #pragma unroll
            for (int q = 0; q < 4; q++) acc[i][j][q] = 0.f;

    auto issue = [&](int it) {
        const char* aS = (const char*)g_Ah + it * 64;
        const char* bS = (const char*)Wh + it * 64;
        const unsigned st = sBase + (it % STAGES) * STAGE_BYTES;
        CP_ASYNC16(st + d0, aS + gA0);
        CP_ASYNC16(st + d1, aS + gA1);
        CP_ASYNC16(st + 8192 + d0, bS + gB0);
        CP_ASYNC16(st + 8192 + d1, bS + gB1);
    };

    issue(0); CP_COMMIT();
    issue(1); CP_COMMIT();

    // ldsm base addresses (stage 0, ks 0)
    const int aRowBase = warpM * 64 + (lane & 15);
    const int bRowBase = warpN * 32 + (lane & 15);
    const int khalf = lane >> 4;
    unsigned aAd[4], bAd[2];
    #pragma unroll
    for (int mf = 0; mf < 4; mf++) aAd[mf] = sBase + SWZ64(aRowBase + mf * 16, khalf);
    #pragma unroll
    for (int nb = 0; nb < 2; nb++) bAd[nb] = sBase + 8192 + SWZ64(bRowBase + nb * 16, khalf);

    for (int it = 0; it < NITER; it++) {
        CP_WAIT1();
        __syncthreads();
        if (it + 2 < NITER) issue(it + 2);   // stage (it+2)%3 == (it-1)%3: all reads done
        CP_COMMIT();

        const unsigned so = (it % STAGES) * STAGE_BYTES;
        #pragma unroll
        for (int ks = 0; ks < 2; ks++) {
            const unsigned kx = ks ? 0x20u : 0u;   // chunk+2 == XOR 0x20
            unsigned af[4][4], bf[2][4];
            #pragma unroll
            for (int mf = 0; mf < 4; mf++)
                LDSM_X4(af[mf][0], af[mf][1], af[mf][2], af[mf][3], (aAd[mf] + so) ^ kx);
            #pragma unroll
            for (int nb = 0; nb < 2; nb++)
                LDSM_X4(bf[nb][0], bf[nb][1], bf[nb][2], bf[nb][3], (bAd[nb] + so) ^ kx);
            #pragma unroll
            for (int mf = 0; mf < 4; mf++)
                #pragma unroll
                for (int nf = 0; nf < 4; nf++) {
                    unsigned b0 = bf[nf >> 1][(nf & 1) ? 1 : 0];
                    unsigned b1 = bf[nf >> 1][(nf & 1) ? 3 : 2];
                    MMA16816(acc[mf][nf], af[mf][0], af[mf][1], af[mf][2], af[mf][3], b0, b1);
                }
        }
    }

    // ---------------- epilogue ----------------
    const int rBase = m0 + warpM * 64 + (lane >> 2);
    const int cBase = n0 + warpN * 32 + (lane & 3) * 2;

    if (z == 0) {
        #pragma unroll
        for (int mf = 0; mf < 4; mf++) {
            #pragma unroll
            for (int nf = 0; nf < 4; nf++) {
                int col = cBase + nf * 8;
                float b0 = biasV[col], b1 = biasV[col + 1];
                int r0 = rBase + mf * 16;
                float2 v;
                v.x = fmaxf(acc[mf][nf][0] + b0, 0.f);
                v.y = fmaxf(acc[mf][nf][1] + b1, 0.f);
                *(float2*)(g_V1 + (size_t)r0 * NKV + col) = v;
                v.x = fmaxf(acc[mf][nf][2] + b0, 0.f);
                v.y = fmaxf(acc[mf][nf][3] + b1, 0.f);
                *(float2*)(g_V1 + (size_t)(r0 + 8) * NKV + col) = v;
            }
        }
    } else {
        __syncthreads();
        float* sdots = (float*)smem_buf;       // [128][2]
        if (tid < 256) sdots[tid] = 0.f;
        __syncthreads();
        const int hloc = warpN >> 1;
        #pragma unroll
        for (int mf = 0; mf < 4; mf++) {
            float slo = 0.f, shi = 0.f;
            #pragma unroll
            for (int nf = 0; nf < 4; nf++) {
                int col = cBase + nf * 8;
                float b0 = biasK[col], b1 = biasK[col + 1];
                float w0 = RH[col],   w1 = RH[col + 1];
                slo += fmaxf(acc[mf][nf][0] + b0, 0.f) * w0
                     + fmaxf(acc[mf][nf][1] + b1, 0.f) * w1;
                shi += fmaxf(acc[mf][nf][2] + b0, 0.f) * w0
                     + fmaxf(acc[mf][nf][3] + b1, 0.f) * w1;
            }
            slo += __shfl_xor_sync(0xffffffffu, slo, 1);
            slo += __shfl_xor_sync(0xffffffffu, slo, 2);
            shi += __shfl_xor_sync(0xffffffffu, shi, 1);
            shi += __shfl_xor_sync(0xffffffffu, shi, 2);
            if ((lane & 3) == 0) {
                int rloc = warpM * 64 + mf * 16 + (lane >> 2);
                atomicAdd(&sdots[rloc * 2 + hloc], slo);
                atomicAdd(&sdots[(rloc + 8) * 2 + hloc], shi);
            }
        }
        __syncthreads();
        if (tid < 256) {
            int rloc = tid >> 1, h = tid & 1;
            int m = m0 + rloc;
            int n = (n0 >> 6) + h;
            float dd = sdots[tid];
            int o = m * NH + n;
            if (fabsf(dd - 0.5f) < MARGIN) {
                int ix = atomicAdd(&g_fixcnt, 1);
                g_fixlist[ix] = (m << 4) | n;
                g_valid[o] = 0;
            } else {
                g_valid[o] = (dd > 0.5f) ? 1 : 0;
            }
        }
    }
}

// ---------------------------------------------------------------------------
// exact fp32 recompute near threshold: one BLOCK per item, k-parallel.
// ---------------------------------------------------------------------------
__global__ __launch_bounds__(256)
void fix_kernel(const float* __restrict__ hs, const float* __restrict__ K1w,
                const float* __restrict__ K1b, const float* __restrict__ RH)
{
    __shared__ float sA[8][64];
    const int cnt = g_fixcnt;
    const int tid = threadIdx.x;
    const int lane = tid & 31, wg = tid >> 5;
    for (int i = blockIdx.x; i < cnt; i += gridDim.x) {
        const int mn = g_fixlist[i];
        const int m = mn >> 4, n = mn & 15;
        const float* a  = hs + (size_t)m * HID + wg * 128;
        const float* wp = K1w + (size_t)(wg * 128) * NKV + n * HD + lane;
        float a0 = 0.f, a1 = 0.f;
        #pragma unroll 8
        for (int k = 0; k < 128; k++) {
            float av = a[k];
            a0 = fmaf(av, wp[(size_t)k * NKV], a0);
            a1 = fmaf(av, wp[(size_t)k * NKV + 32], a1);
        }
        sA[wg][lane]      = a0;
        sA[wg][lane + 32] = a1;
        __syncthreads();
        if (tid < 64) {
            float s = 0.f;
            #pragma unroll
            for (int w = 0; w < 8; w++) s += sA[w][tid];
            s = fmaxf(s + K1b[n * HD + tid], 0.f) * RH[n * HD + tid];
            sA[0][tid] = s;
        }
        __syncthreads();
        if (tid == 0) {
            float d = 0.f;
            #pragma unroll
            for (int c = 0; c < 64; c++) d += sA[0][c];
            g_valid[m * NH + n] = (d > 0.5f) ? 1 : 0;
        }
        __syncthreads();
    }
}

// ---------------------------------------------------------------------------
// parallel scan via prefix/suffix max (exact reference semantics)
// ---------------------------------------------------------------------------
__global__ __launch_bounds__(256)
void scan_kernel()
{
    __shared__ int pm[LEN];
    __shared__ int sx[LEN];
    __shared__ int tpart[256];
    const int b = blockIdx.x >> 4;
    const int n = blockIdx.x & 15;
    const int tid = threadIdx.x;

    unsigned char v8[8];
    #pragma unroll
    for (int j = 0; j < 8; j++)
        v8[j] = g_valid[(size_t)(b * LEN + tid * 8 + j) * NH + n];

    // forward prefix max
    {
        int run = 0, loc[8];
        #pragma unroll
        for (int j = 0; j < 8; j++) {
            int l = tid * 8 + j;
            int a = (v8[j] && l >= 1) ? l : 0;
            run = max(run, a);
            loc[j] = run;
        }
        tpart[tid] = run;
        __syncthreads();
        int acc = tpart[tid];
        #pragma unroll
        for (int of = 1; of < 256; of <<= 1) {
            int o = (tid >= of) ? tpart[tid - of] : 0;
            __syncthreads();
            acc = max(acc, o);
            tpart[tid] = acc;
            __syncthreads();
        }
        int pre = (tid > 0) ? tpart[tid - 1] : 0;
        #pragma unroll
        for (int j = 0; j < 8; j++) pm[tid * 8 + j] = max(pre, loc[j]);
    }
    __syncthreads();
    // backward suffix max (values L-1-l, positions l<=L-2)
    {
        int run = 0, loc[8];
        #pragma unroll
        for (int j = 7; j >= 0; j--) {
            int l = tid * 8 + j;
            int a = (v8[j] && l <= LEN - 2) ? (LEN - 1 - l) : 0;
            run = max(run, a);
            loc[j] = run;
        }
        tpart[tid] = run;
        __syncthreads();
        int acc = tpart[tid];
        #pragma unroll
        for (int of = 1; of < 256; of <<= 1) {
            int o = (tid + of < 256) ? tpart[tid + of] : 0;
            __syncthreads();
            acc = max(acc, o);
            tpart[tid] = acc;
            __syncthreads();
        }
        int suf = (tid < 255) ? tpart[tid + 1] : 0;
        #pragma unroll
        for (int j = 0; j < 8; j++) sx[tid * 8 + j] = max(suf, loc[j]);
    }
    __syncthreads();

    #pragma unroll
    for (int j = 0; j < 8; j++) {
        int l = tid * 8 + j;
        const size_t o = (size_t)(b * LEN + l) * NH + n;
        int fa = pm[l];
        int fb = (fa > 0) ? pm[fa - 1] : 0;
        g_fm[o] = make_int2(fa, fb);
        int s = sx[l];
        int ba, bb;
        if (s == 0) { ba = LEN - 1; bb = LEN - 1; }
        else {
            ba = s;
            int l2 = (LEN - 1) - s;
            int s2 = (l2 + 1 <= LEN - 1) ? sx[l2 + 1] : 0;
            bb = (s2 == 0) ? (LEN - 1) : s2;
        }
        g_bm[o] = make_int2(ba, bb);
    }
}

// ---------------------------------------------------------------------------
__global__ void gather_kernel(const float* __restrict__ bw, float* __restrict__ out)
{
    const int t = blockIdx.x * blockDim.x + threadIdx.x;
    const int h4 = t & 15;
    const int n  = (t >> 4) & 15;
    const int m  = t >> 8;
    if (m >= MTOT) return;
    const int b = m >> 11;
    const size_t io = (size_t)m * NH + n;
    const int2 f  = g_fm[io];
    const int2 bk = g_bm[io];
    const float4 w = *(const float4*)(bw + n * 4);
    const int base = b * LEN;
    const int col = n * HD + h4 * 4;
    const float4 v0 = *(const float4*)(g_V1 + (size_t)(base + f.x)  * NKV + col);
    const float4 v1 = *(const float4*)(g_V1 + (size_t)(base + f.y)  * NKV + col);
    const float4 v2 = *(const float4*)(g_V1 + (size_t)(base + bk.x) * NKV + col);
    const float4 v3 = *(const float4*)(g_V1 + (size_t)(base + bk.y) * NKV + col);
    float4 rr;
    rr.x = w.x * v0.x + w.y * v1.x + w.z * v2.x + w.w * v3.x;
    rr.y = w.x * v0.y + w.y * v1.y + w.z * v2.y + w.w * v3.y;
    rr.z = w.x * v0.z + w.y * v1.z + w.z * v2.z + w.w * v3.z;
    rr.w = w.x * v0.w + w.y * v1.w + w.z * v2.w + w.w * v3.w;
    *(float4*)(out + (size_t)m * NKV + col) = rr;
}

// ---------------------------------------------------------------------------
extern "C" void kernel_launch(void* const* d_in, const int* in_sizes, int n_in,
                              void* d_out, int out_size)
{
    const float* hs  = (const float*)d_in[0];
    const float* K1w = (const float*)d_in[1];
    const float* K1b = (const float*)d_in[2];
    const float* V1w = (const float*)d_in[3];
    const float* V1b = (const float*)d_in[4];
    const float* bw  = (const float*)d_in[5];
    const float* RH  = (const float*)d_in[6];
    float* out = (float*)d_out;

    convA_kernel<<<(MTOT * HID / 8) / 256, 256>>>(hs);
    convW_kernel<<<dim3(32, 32, 2), 256>>>(V1w, K1w);
    mma_kernel<<<dim3(16, MTOT / BM), 256>>>(V1b, K1b, RH);
    fix_kernel<<<2048, 256>>>(hs, K1w, K1b, RH);
    scan_kernel<<<BSZ * NH, 256>>>();
    gather_kernel<<<(MTOT * NH * 16) / 256, 256>>>(bw, out);
}